// round 3
// baseline (speedup 1.0000x reference)
#include <cuda_runtime.h>

typedef unsigned long long u64;

#define B_SZ 256
#define N_SZ 50
#define NN   (N_SZ * N_SZ)
#define MAX_ATTR 2000
#define NEGV (-9e15f)
#define NTHREADS 512
#define ATTR_BLOCKS 64
#define ATTR_ROWS 4
#define ATTR_SEGS 4
#define KSEG (MAX_ATTR / ATTR_SEGS)   // 500
#define HSTRIDE 65          // u64 stride per h row (520B -> conflict-free LDS.64)
#define APAD 52

// ---- packed f32x2 helpers (Blackwell) -------------------------------------
__device__ __forceinline__ u64 f2_fma(u64 a, u64 b, u64 c) {
    u64 d; asm("fma.rn.f32x2 %0,%1,%2,%3;" : "=l"(d) : "l"(a), "l"(b), "l"(c)); return d;
}
__device__ __forceinline__ u64 f2_mul(u64 a, u64 b) {
    u64 d; asm("mul.rn.f32x2 %0,%1,%2;" : "=l"(d) : "l"(a), "l"(b)); return d;
}
__device__ __forceinline__ u64 f2_add(u64 a, u64 b) {
    u64 d; asm("add.rn.f32x2 %0,%1,%2;" : "=l"(d) : "l"(a), "l"(b)); return d;
}
__device__ __forceinline__ u64 f2_abs(u64 a) { return a & 0x7FFFFFFF7FFFFFFFull; }
__device__ __forceinline__ u64 f2_dup(float a) {
    u64 d; asm("mov.b64 %0,{%1,%1};" : "=l"(d) : "f"(a)); return d;
}
__device__ __forceinline__ float2 f2_unpack(u64 a) {
    float2 r; asm("mov.b64 {%0,%1},%2;" : "=f"(r.x), "=f"(r.y) : "l"(a)); return r;
}
__device__ __forceinline__ float pq_combine(u64 Pa, u64 Pb, u64 Qa, u64 Qb) {
    float2 p = f2_unpack(f2_add(Pa, Pb));
    float2 q = f2_unpack(f2_add(Qa, Qb));
    return 0.6f * (p.x + p.y) + 0.4f * (q.x + q.y);
}

struct SessSmem {
    u64  hu[N_SZ * HSTRIDE];        // 26000 B
    u64  a4t[32 * 4 * 2];           //  2048 B  [c][k][lo/hi]
    float alpha[N_SZ * APAD];       // 10400 B
    unsigned char adjs[NN + 12];    //  2512 B
};
struct AttrSmem {
    u64 red[(ATTR_SEGS - 1) * ATTR_ROWS * 64];  // 6144 B
};

__global__ __launch_bounds__(NTHREADS, 2)
void session_graph_kernel(const int* __restrict__ inputs,
                          const int* __restrict__ adj,
                          const float* __restrict__ A_attr,
                          const float* __restrict__ emb,
                          const float* __restrict__ attr_emb,
                          const float* __restrict__ a0,
                          const float* __restrict__ a1,
                          const float* __restrict__ a2,
                          const float* __restrict__ a3,
                          float* __restrict__ out)
{
    __shared__ union { SessSmem s; AttrSmem g; } sm;

    const int tid  = threadIdx.x;
    const int bb   = blockIdx.x;
    const int warp = tid >> 5;
    const int lane = tid & 31;

    if (bb < B_SZ) {
        // ---------------- stage a4t, adj (bytes), h -----------------------
        if (tid < 128) {
            int k = tid >> 5, c = tid & 31;
            const float* asrc = (k == 0) ? a0 : (k == 1) ? a1 : (k == 2) ? a2 : a3;
            const u64* au = (const u64*)asrc;
            sm.s.a4t[(c * 4 + k) * 2 + 0] = au[2 * c];
            sm.s.a4t[(c * 4 + k) * 2 + 1] = au[2 * c + 1];
        }
        {
            const int* ag = adj + bb * NN;
            for (int idx = tid; idx < NN; idx += NTHREADS)
                sm.s.adjs[idx] = (unsigned char)ag[idx];
        }
        {
            const int* inrow = inputs + bb * N_SZ;
            const u64* embu = (const u64*)emb;
            for (int idx = tid; idx < N_SZ * 64; idx += NTHREADS) {
                int i = idx >> 6, c = idx & 63;
                int node = inrow[i];
                sm.s.hu[i * HSTRIDE + c] = embu[(size_t)node * 64 + c];
            }
        }
        __syncthreads();

        // ---------------- phase 2: logits + softmax (row pairs) -----------
        const u64* __restrict__ hu = sm.s.hu;
        for (int base = 0; base < N_SZ; base += 32) {
            int r0 = base + 2 * warp;
            int r1 = r0 + 1;
            if (r1 < N_SZ) {
                const u64* px0 = hu + r0 * HSTRIDE;   // broadcast reads
                const u64* px1 = hu + r1 * HSTRIDE;
                float sres[2][2];                      // [row][half]
                int   code[2][2];
                bool  act1 = (lane + 32 < N_SZ);

                #pragma unroll
                for (int half = 0; half < 2; ++half) {
                    int je = lane + 32 * half;
                    int j  = (je < N_SZ) ? je : 0;
                    int c0 = sm.s.adjs[r0 * N_SZ + j];
                    int c1 = sm.s.adjs[r1 * N_SZ + j];
                    code[0][half] = c0;
                    code[1][half] = c1;
                    const u64* pav0 = sm.s.a4t + ((c0 > 0 ? c0 - 1 : 0) << 1);
                    const u64* pav1 = sm.s.a4t + ((c1 > 0 ? c1 - 1 : 0) << 1);
                    const u64* py   = hu + j * HSTRIDE;

                    u64 P0a = 0, P0b = 0, Q0a = 0, Q0b = 0;
                    u64 P1a = 0, P1b = 0, Q1a = 0, Q1b = 0;
                    #pragma unroll 4
                    for (int c = 0; c < 32; ++c) {
                        u64 ya  = py[2 * c], yb = py[2 * c + 1];
                        u64 x0a = px0[2 * c], x0b = px0[2 * c + 1];
                        u64 x1a = px1[2 * c], x1b = px1[2 * c + 1];
                        u64 a0a = pav0[c * 8], a0b = pav0[c * 8 + 1];
                        u64 a1a = pav1[c * 8], a1b = pav1[c * 8 + 1];
                        u64 v;
                        v = f2_mul(x0a, ya); P0a = f2_fma(v, a0a, P0a); Q0a = f2_fma(f2_abs(v), a0a, Q0a);
                        v = f2_mul(x0b, yb); P0b = f2_fma(v, a0b, P0b); Q0b = f2_fma(f2_abs(v), a0b, Q0b);
                        v = f2_mul(x1a, ya); P1a = f2_fma(v, a1a, P1a); Q1a = f2_fma(f2_abs(v), a1a, Q1a);
                        v = f2_mul(x1b, yb); P1b = f2_fma(v, a1b, P1b); Q1b = f2_fma(f2_abs(v), a1b, Q1b);
                    }
                    sres[0][half] = pq_combine(P0a, P0b, Q0a, Q0b);
                    sres[1][half] = pq_combine(P1a, P1b, Q1a, Q1b);
                }

                #pragma unroll
                for (int r = 0; r < 2; ++r) {
                    int row = (r == 0) ? r0 : r1;
                    float v0 = (code[r][0] != 0) ? sres[r][0] : NEGV;
                    float v1 = (act1 && code[r][1] != 0) ? sres[r][1] : NEGV;
                    float m = fmaxf(v0, v1);
                    #pragma unroll
                    for (int off = 16; off > 0; off >>= 1)
                        m = fmaxf(m, __shfl_xor_sync(0xFFFFFFFFu, m, off));
                    float e0 = __expf(v0 - m);
                    float e1 = act1 ? __expf(v1 - m) : 0.f;
                    float ss = e0 + e1;
                    #pragma unroll
                    for (int off = 16; off > 0; off >>= 1)
                        ss += __shfl_xor_sync(0xFFFFFFFFu, ss, off);
                    float inv = 1.0f / ss;
                    sm.s.alpha[row * APAD + lane] = e0 * inv;
                    if (act1) sm.s.alpha[row * APAD + 32 + lane] = e1 * inv;
                }
            }
        }
        __syncthreads();

        // ---------------- phase 4: out = alpha @ h (row pairs, packed) ----
        u64* outu = (u64*)out;
        for (int base = 0; base < N_SZ; base += 32) {
            int r0 = base + 2 * warp;
            int r1 = r0 + 1;
            if (r1 < N_SZ) {
                const float* ar0 = &sm.s.alpha[r0 * APAD];
                const float* ar1 = &sm.s.alpha[r1 * APAD];
                u64 aL0 = 0, aH0 = 0, aL1 = 0, aH1 = 0;
                #pragma unroll 5
                for (int j = 0; j < N_SZ; ++j) {
                    u64 hlo = hu[j * HSTRIDE + lane];
                    u64 hhi = hu[j * HSTRIDE + 32 + lane];
                    u64 d0 = f2_dup(ar0[j]);
                    u64 d1 = f2_dup(ar1[j]);
                    aL0 = f2_fma(d0, hlo, aL0);
                    aH0 = f2_fma(d0, hhi, aH0);
                    aL1 = f2_fma(d1, hlo, aL1);
                    aH1 = f2_fma(d1, hhi, aH1);
                }
                size_t ob = (size_t)bb * (N_SZ * 64);
                outu[ob + r0 * 64 + lane]      = aL0;
                outu[ob + r0 * 64 + 32 + lane] = aH0;
                outu[ob + r1 * 64 + lane]      = aL1;
                outu[ob + r1 * 64 + 32 + lane] = aH1;
            }
        }
    } else {
        // ---------------- attr_sess = A_attr @ attr_emb (packed) ----------
        const int ab  = bb - B_SZ;
        const int r0  = ab * ATTR_ROWS;
        const int row = warp & (ATTR_ROWS - 1);
        const int seg = warp >> 2;

        const float* Arow = A_attr + (size_t)(r0 + row) * MAX_ATTR + seg * KSEG;
        const u64*   Wu   = ((const u64*)attr_emb) + (size_t)seg * KSEG * 64;

        u64 acc0 = 0, acc1 = 0;
        #pragma unroll 4
        for (int k = 0; k < KSEG; ++k) {
            u64 ad = f2_dup(Arow[k]);
            u64 w0 = Wu[(size_t)k * 64 + 2 * lane];
            u64 w1 = Wu[(size_t)k * 64 + 2 * lane + 1];
            acc0 = f2_fma(ad, w0, acc0);
            acc1 = f2_fma(ad, w1, acc1);
        }
        if (seg > 0) {
            sm.g.red[((seg - 1) * ATTR_ROWS + row) * 64 + 2 * lane]     = acc0;
            sm.g.red[((seg - 1) * ATTR_ROWS + row) * 64 + 2 * lane + 1] = acc1;
        }
        __syncthreads();
        if (seg == 0) {
            #pragma unroll
            for (int s2 = 0; s2 < ATTR_SEGS - 1; ++s2) {
                acc0 = f2_add(acc0, sm.g.red[(s2 * ATTR_ROWS + row) * 64 + 2 * lane]);
                acc1 = f2_add(acc1, sm.g.red[(s2 * ATTR_ROWS + row) * 64 + 2 * lane + 1]);
            }
            u64* outu = (u64*)out;
            size_t ob = (size_t)B_SZ * (N_SZ * 64) + (size_t)(r0 + row) * 64;
            outu[ob + 2 * lane]     = acc0;
            outu[ob + 2 * lane + 1] = acc1;
        }
    }
}

extern "C" void kernel_launch(void* const* d_in, const int* in_sizes, int n_in,
                              void* d_out, int out_size)
{
    (void)in_sizes; (void)n_in; (void)out_size;
    const int*   inputs    = (const int*)  d_in[0];
    const int*   adj       = (const int*)  d_in[1];
    // d_in[2] = mask_item (unused by the reference computation)
    const float* A_attr    = (const float*)d_in[3];
    const float* emb       = (const float*)d_in[4];
    const float* attr_emb  = (const float*)d_in[5];
    const float* a0        = (const float*)d_in[6];
    const float* a1        = (const float*)d_in[7];
    const float* a2        = (const float*)d_in[8];
    const float* a3        = (const float*)d_in[9];
    float* out = (float*)d_out;

    session_graph_kernel<<<B_SZ + ATTR_BLOCKS, NTHREADS>>>(
        inputs, adj, A_attr, emb, attr_emb, a0, a1, a2, a3, out);
}

// round 4
// speedup vs baseline: 1.2057x; 1.2057x over previous
#include <cuda_runtime.h>

typedef unsigned long long u64;
typedef unsigned int u32;

#define B_SZ 256
#define N_SZ 50
#define NN   (N_SZ * N_SZ)
#define MAX_ATTR 2000
#define NEGV (-9e15f)
#define NTHREADS 512
#define ATTR_BLOCKS 64
#define HSTR 66                 // u64 stride per h row
#define ASTR 56                 // alpha row stride (f32)
#define AFSTR 260               // a' row stride (f32)

// ---- packed f32x2 helpers --------------------------------------------------
__device__ __forceinline__ u64 f2_fma(u64 a, u64 b, u64 c) {
    u64 d; asm("fma.rn.f32x2 %0,%1,%2,%3;" : "=l"(d) : "l"(a), "l"(b), "l"(c)); return d;
}
__device__ __forceinline__ u64 f2_mul(u64 a, u64 b) {
    u64 d; asm("mul.rn.f32x2 %0,%1,%2;" : "=l"(d) : "l"(a), "l"(b)); return d;
}
__device__ __forceinline__ u64 f2_add(u64 a, u64 b) {
    u64 d; asm("add.rn.f32x2 %0,%1,%2;" : "=l"(d) : "l"(a), "l"(b)); return d;
}
__device__ __forceinline__ u64 f2_abs(u64 a) { return a & 0x7FFFFFFF7FFFFFFFull; }
__device__ __forceinline__ u64 f2_dup(float a) {
    u64 d; asm("mov.b64 %0,{%1,%1};" : "=l"(d) : "f"(a)); return d;
}
__device__ __forceinline__ u64 f2_pack(float x, float y) {
    u64 d; asm("mov.b64 %0,{%1,%2};" : "=l"(d) : "f"(x), "f"(y)); return d;
}
__device__ __forceinline__ float2 f2_unpack(u64 a) {
    float2 r; asm("mov.b64 {%0,%1},%2;" : "=f"(r.x), "=f"(r.y) : "l"(a)); return r;
}
// pack (lo=col c, hi=col c+1) fp32 pair -> bf16x2 (lo in low half)
__device__ __forceinline__ u32 bcvt(u64 v) {
    float2 p = f2_unpack(v);
    u32 r; asm("cvt.rn.bf16x2.f32 %0,%1,%2;" : "=r"(r) : "f"(p.y), "f"(p.x)); return r;
}
__device__ __forceinline__ void mma16816(float& d0, float& d1, float& d2, float& d3,
                                         u32 a0, u32 a1, u32 a2, u32 a3, u32 b0, u32 b1) {
    asm("mma.sync.aligned.m16n8k16.row.col.f32.bf16.bf16.f32 "
        "{%0,%1,%2,%3},{%4,%5,%6,%7},{%8,%9},{%0,%1,%2,%3};"
        : "+f"(d0), "+f"(d1), "+f"(d2), "+f"(d3)
        : "r"(a0), "r"(a1), "r"(a2), "r"(a3), "r"(b0), "r"(b1));
}

struct SessSmem {
    u64   hu[56 * HSTR];         // 29568 B  h rows fp32 (as u64 pairs), rows 50..55 junk-pad
    float af[4 * AFSTR];         //  4160 B  a'[k][c]: c<128 -> 0.6*a_k[c], else 0.4*a_k[c-128]
    float alpha[N_SZ * ASTR];    // 11200 B
    unsigned char adjb[NN + 12]; //  2512 B
};
struct AttrSmem {
    u64 red[16 * 4 * 64];        // 32768 B
};

__global__ __launch_bounds__(NTHREADS, 2)
void session_graph_kernel(const int* __restrict__ inputs,
                          const int* __restrict__ adj,
                          const float* __restrict__ A_attr,
                          const float* __restrict__ emb,
                          const float* __restrict__ attr_emb,
                          const float* __restrict__ a0,
                          const float* __restrict__ a1,
                          const float* __restrict__ a2,
                          const float* __restrict__ a3,
                          float* __restrict__ out)
{
    __shared__ union { SessSmem s; AttrSmem g; } sm;

    const int tid  = threadIdx.x;
    const int bb   = blockIdx.x;
    const int warp = tid >> 5;
    const int lane = tid & 31;
    const int gq   = lane >> 2;   // 0..7
    const int tq   = lane & 3;    // 0..3

    if (bb < B_SZ) {
        // ---------------- stage a' table, adj bytes, h, alpha=NEGV --------
        if (tid < 512) {          // exactly 4k*128c
            int k = tid >> 7, c = tid & 127;
            const float* a = (k == 0) ? a0 : (k == 1) ? a1 : (k == 2) ? a2 : a3;
            float v = a[c];
            sm.s.af[k * AFSTR + c]       = 0.6f * v;
            sm.s.af[k * AFSTR + 128 + c] = 0.4f * v;
        }
        {
            const int* ag = adj + bb * NN;
            for (int idx = tid; idx < NN; idx += NTHREADS)
                sm.s.adjb[idx] = (unsigned char)ag[idx];
        }
        {
            const int* inrow = inputs + bb * N_SZ;
            const u64* embu = (const u64*)emb;
            for (int idx = tid; idx < N_SZ * 64; idx += NTHREADS) {
                int i = idx >> 6, c = idx & 63;
                int node = inrow[i];
                sm.s.hu[i * HSTR + c] = embu[(size_t)node * 64 + c];
            }
        }
        for (int idx = tid; idx < N_SZ * ASTR; idx += NTHREADS)
            sm.s.alpha[idx] = NEGV;
        __syncthreads();

        // ---------------- phase 2: E = A' B'^T via bf16 MMA ----------------
        // M = 200 (k*50+i), 13 mtiles; N = 50->56, 7 ntiles; K = 256, 16 steps
        for (int tile = warp; tile < 91; tile += 16) {
            int mt = tile / 7, nt = tile - mt * 7;
            int r0 = mt * 16 + gq;
            int r1 = r0 + 8;
            int r1c = (r1 < 200) ? r1 : 199;
            int k0 = r0 / 50,  i0 = r0 - k0 * 50;
            int k1 = r1c / 50, i1 = r1c - k1 * 50;
            const u64* ph0 = sm.s.hu + i0 * HSTR;
            const u64* ph1 = sm.s.hu + i1 * HSTR;
            const u64* pa0 = (const u64*)(sm.s.af + k0 * AFSTR);
            const u64* pa1 = (const u64*)(sm.s.af + k1 * AFSTR);
            const u64* pb  = sm.s.hu + (nt * 8 + gq) * HSTR;
            float d0 = 0.f, d1 = 0.f, d2 = 0.f, d3 = 0.f;

            #pragma unroll
            for (int ks = 0; ks < 8; ++ks) {            // cols 0..127 (plain h)
                int x = 8 * ks + tq;
                u32 fa0 = bcvt(f2_mul(ph0[x],     pa0[x]));
                u32 fa1 = bcvt(f2_mul(ph1[x],     pa1[x]));
                u32 fa2 = bcvt(f2_mul(ph0[x + 4], pa0[x + 4]));
                u32 fa3 = bcvt(f2_mul(ph1[x + 4], pa1[x + 4]));
                u32 fb0 = bcvt(pb[x]);
                u32 fb1 = bcvt(pb[x + 4]);
                mma16816(d0, d1, d2, d3, fa0, fa1, fa2, fa3, fb0, fb1);
            }
            #pragma unroll
            for (int ks = 0; ks < 8; ++ks) {            // cols 128..255 (|h|)
                int x  = 8 * ks + tq;
                int xa = x + 64;
                u32 fa0 = bcvt(f2_mul(f2_abs(ph0[x]),     pa0[xa]));
                u32 fa1 = bcvt(f2_mul(f2_abs(ph1[x]),     pa1[xa]));
                u32 fa2 = bcvt(f2_mul(f2_abs(ph0[x + 4]), pa0[xa + 4]));
                u32 fa3 = bcvt(f2_mul(f2_abs(ph1[x + 4]), pa1[xa + 4]));
                u32 fb0 = bcvt(f2_abs(pb[x]));
                u32 fb1 = bcvt(f2_abs(pb[x + 4]));
                mma16816(d0, d1, d2, d3, fa0, fa1, fa2, fa3, fb0, fb1);
            }

            // epilogue: masked select into alpha
            int j0 = nt * 8 + 2 * tq;
            if (j0 < N_SZ) {
                bool j1ok = (j0 + 1 < N_SZ);
                if (sm.s.adjb[i0 * N_SZ + j0] == k0 + 1)          sm.s.alpha[i0 * ASTR + j0]     = d0;
                if (j1ok && sm.s.adjb[i0 * N_SZ + j0 + 1] == k0 + 1) sm.s.alpha[i0 * ASTR + j0 + 1] = d1;
                if (r1 < 200) {
                    if (sm.s.adjb[i1 * N_SZ + j0] == k1 + 1)          sm.s.alpha[i1 * ASTR + j0]     = d2;
                    if (j1ok && sm.s.adjb[i1 * N_SZ + j0 + 1] == k1 + 1) sm.s.alpha[i1 * ASTR + j0 + 1] = d3;
                }
            }
        }
        __syncthreads();

        // ---------------- phase 3: row softmax ----------------------------
        for (int i = warp; i < N_SZ; i += 16) {
            float v0 = sm.s.alpha[i * ASTR + lane];
            float v1 = (lane < N_SZ - 32) ? sm.s.alpha[i * ASTR + 32 + lane] : NEGV;
            float m = fmaxf(v0, v1);
            #pragma unroll
            for (int off = 16; off > 0; off >>= 1)
                m = fmaxf(m, __shfl_xor_sync(0xFFFFFFFFu, m, off));
            float e0 = __expf(v0 - m);
            float e1 = (lane < N_SZ - 32) ? __expf(v1 - m) : 0.f;
            float ss = e0 + e1;
            #pragma unroll
            for (int off = 16; off > 0; off >>= 1)
                ss += __shfl_xor_sync(0xFFFFFFFFu, ss, off);
            float inv = 1.0f / ss;
            sm.s.alpha[i * ASTR + lane] = e0 * inv;
            if (lane < N_SZ - 32)
                sm.s.alpha[i * ASTR + 32 + lane] = e1 * inv;
        }
        __syncthreads();

        // ---------------- phase 4: out = alpha @ h (fp32 packed) ----------
        u64* outu = (u64*)out;
        const u64* hu = sm.s.hu;
        for (int base = 0; base < N_SZ; base += 32) {
            int r0 = base + 2 * warp;
            int r1 = r0 + 1;
            if (r1 < N_SZ) {
                const float* ar0 = &sm.s.alpha[r0 * ASTR];
                const float* ar1 = &sm.s.alpha[r1 * ASTR];
                u64 aL0 = 0, aH0 = 0, aL1 = 0, aH1 = 0;
                #pragma unroll 5
                for (int j = 0; j < N_SZ; ++j) {
                    u64 hlo = hu[j * HSTR + lane];
                    u64 hhi = hu[j * HSTR + 32 + lane];
                    u64 c0 = f2_dup(ar0[j]);
                    u64 c1 = f2_dup(ar1[j]);
                    aL0 = f2_fma(c0, hlo, aL0);
                    aH0 = f2_fma(c0, hhi, aH0);
                    aL1 = f2_fma(c1, hlo, aL1);
                    aH1 = f2_fma(c1, hhi, aH1);
                }
                size_t ob = (size_t)bb * (N_SZ * 64);
                outu[ob + r0 * 64 + lane]      = aL0;
                outu[ob + r0 * 64 + 32 + lane] = aH0;
                outu[ob + r1 * 64 + lane]      = aL1;
                outu[ob + r1 * 64 + 32 + lane] = aH1;
            }
        }
    } else {
        // ---------------- attr_sess = A_attr @ attr_emb --------------------
        // warp = K segment (125 k each); rows r0..r0+3 looped inside.
        const int ab    = bb - B_SZ;
        const int r0row = ab * 4;
        const int kbase = warp * 125;
        const float4* W4 = ((const float4*)attr_emb);
        const float* Ar0 = A_attr + (size_t)(r0row + 0) * MAX_ATTR + kbase;
        const float* Ar1 = A_attr + (size_t)(r0row + 1) * MAX_ATTR + kbase;
        const float* Ar2 = A_attr + (size_t)(r0row + 2) * MAX_ATTR + kbase;
        const float* Ar3 = A_attr + (size_t)(r0row + 3) * MAX_ATTR + kbase;

        u64 acc[4][2] = {{0,0},{0,0},{0,0},{0,0}};
        #pragma unroll 5
        for (int k = 0; k < 125; ++k) {
            float4 w = W4[(size_t)(kbase + k) * 32 + lane];
            u64 wl = f2_pack(w.x, w.y);
            u64 wh = f2_pack(w.z, w.w);
            u64 c0 = f2_dup(Ar0[k]);
            u64 c1 = f2_dup(Ar1[k]);
            u64 c2 = f2_dup(Ar2[k]);
            u64 c3 = f2_dup(Ar3[k]);
            acc[0][0] = f2_fma(c0, wl, acc[0][0]); acc[0][1] = f2_fma(c0, wh, acc[0][1]);
            acc[1][0] = f2_fma(c1, wl, acc[1][0]); acc[1][1] = f2_fma(c1, wh, acc[1][1]);
            acc[2][0] = f2_fma(c2, wl, acc[2][0]); acc[2][1] = f2_fma(c2, wh, acc[2][1]);
            acc[3][0] = f2_fma(c3, wl, acc[3][0]); acc[3][1] = f2_fma(c3, wh, acc[3][1]);
        }
        #pragma unroll
        for (int r = 0; r < 4; ++r) {
            sm.g.red[((warp * 4) + r) * 64 + 2 * lane]     = acc[r][0];
            sm.g.red[((warp * 4) + r) * 64 + 2 * lane + 1] = acc[r][1];
        }
        __syncthreads();
        if (warp < 4) {
            int row = warp;
            u64 s0 = 0, s1 = 0;
            #pragma unroll
            for (int s = 0; s < 16; ++s) {
                s0 = f2_add(s0, sm.g.red[(s * 4 + row) * 64 + 2 * lane]);
                s1 = f2_add(s1, sm.g.red[(s * 4 + row) * 64 + 2 * lane + 1]);
            }
            u64* outu = (u64*)out;
            size_t ob = (size_t)B_SZ * (N_SZ * 64) + (size_t)(r0row + row) * 64;
            outu[ob + 2 * lane]     = s0;
            outu[ob + 2 * lane + 1] = s1;
        }
    }
}

extern "C" void kernel_launch(void* const* d_in, const int* in_sizes, int n_in,
                              void* d_out, int out_size)
{
    (void)in_sizes; (void)n_in; (void)out_size;
    const int*   inputs    = (const int*)  d_in[0];
    const int*   adj       = (const int*)  d_in[1];
    // d_in[2] = mask_item (unused by the reference computation)
    const float* A_attr    = (const float*)d_in[3];
    const float* emb       = (const float*)d_in[4];
    const float* attr_emb  = (const float*)d_in[5];
    const float* a0        = (const float*)d_in[6];
    const float* a1        = (const float*)d_in[7];
    const float* a2        = (const float*)d_in[8];
    const float* a3        = (const float*)d_in[9];
    float* out = (float*)d_out;

    session_graph_kernel<<<B_SZ + ATTR_BLOCKS, NTHREADS>>>(
        inputs, adj, A_attr, emb, attr_emb, a0, a1, a2, a3, out);
}

// round 5
// speedup vs baseline: 2.1076x; 1.7481x over previous
#include <cuda_runtime.h>

typedef unsigned long long u64;
typedef unsigned int u32;

#define B_SZ 256
#define N_SZ 50
#define NN   (N_SZ * N_SZ)
#define MAX_ATTR 2000
#define NEGV (-9e15f)
#define NTHREADS 512
#define ATTR_BLOCKS 64
#define HBSTR 528               // bytes per hb16 row (264 bf16; 528%128=16 -> LDSM conflict-free)
#define HUSTR 65                // u64 stride per fp32 h row
#define ASTR  56                // alpha row stride (f32)

// ---- dynamic smem layout ---------------------------------------------------
#define OFF_HB16  0
#define SZ_HB16   (56 * HBSTR)                 // 29568
#define OFF_HU    (OFF_HB16 + SZ_HB16)
#define SZ_HU     (N_SZ * HUSTR * 8)           // 26000
#define OFF_AB2   (OFF_HU + SZ_HU)
#define SZ_AB2    (4 * 16 * 4 * 8)             // 2048
#define OFF_ALPHA (OFF_AB2 + SZ_AB2)
#define SZ_ALPHA  (N_SZ * ASTR * 4)            // 11200
#define OFF_ADJ   (OFF_ALPHA + SZ_ALPHA)
#define SZ_ADJ    2560
#define SMEM_DYN  (OFF_ADJ + SZ_ADJ)           // 71376

// ---- helpers ---------------------------------------------------------------
__device__ __forceinline__ u64 f2_fma(u64 a, u64 b, u64 c) {
    u64 d; asm("fma.rn.f32x2 %0,%1,%2,%3;" : "=l"(d) : "l"(a), "l"(b), "l"(c)); return d;
}
__device__ __forceinline__ u64 f2_add(u64 a, u64 b) {
    u64 d; asm("add.rn.f32x2 %0,%1,%2;" : "=l"(d) : "l"(a), "l"(b)); return d;
}
__device__ __forceinline__ u64 f2_abs(u64 a) { return a & 0x7FFFFFFF7FFFFFFFull; }
__device__ __forceinline__ u64 f2_dup(float a) {
    u64 d; asm("mov.b64 %0,{%1,%1};" : "=l"(d) : "f"(a)); return d;
}
__device__ __forceinline__ u64 f2_pack(float x, float y) {
    u64 d; asm("mov.b64 %0,{%1,%2};" : "=l"(d) : "f"(x), "f"(y)); return d;
}
__device__ __forceinline__ float2 f2_unpack(u64 a) {
    float2 r; asm("mov.b64 {%0,%1},%2;" : "=f"(r.x), "=f"(r.y) : "l"(a)); return r;
}
__device__ __forceinline__ u32 bpack(float lo, float hi) {   // lo -> low half
    u32 r; asm("cvt.rn.bf16x2.f32 %0,%1,%2;" : "=r"(r) : "f"(hi), "f"(lo)); return r;
}
__device__ __forceinline__ u32 bcvt(u64 v) {                 // 2xfp32 -> bf16x2
    float2 p = f2_unpack(v); return bpack(p.x, p.y);
}
__device__ __forceinline__ u32 bmul(u32 a, u32 b) {
    u32 d; asm("mul.bf16x2 %0,%1,%2;" : "=r"(d) : "r"(a), "r"(b)); return d;
}
__device__ __forceinline__ u32 s2u(const void* p) {
    u32 a; asm("{.reg .u64 t; cvta.to.shared.u64 t,%1; cvt.u32.u64 %0,t;}" : "=r"(a) : "l"(p));
    return a;
}
__device__ __forceinline__ void ldsm4(u32& r0, u32& r1, u32& r2, u32& r3, u32 addr) {
    asm volatile("ldmatrix.sync.aligned.m8n8.x4.shared.b16 {%0,%1,%2,%3},[%4];"
                 : "=r"(r0), "=r"(r1), "=r"(r2), "=r"(r3) : "r"(addr));
}
__device__ __forceinline__ void ldsm2(u32& r0, u32& r1, u32 addr) {
    asm volatile("ldmatrix.sync.aligned.m8n8.x2.shared.b16 {%0,%1},[%2];"
                 : "=r"(r0), "=r"(r1) : "r"(addr));
}
__device__ __forceinline__ void mma16816(float& d0, float& d1, float& d2, float& d3,
                                         u32 a0, u32 a1, u32 a2, u32 a3, u32 b0, u32 b1) {
    asm("mma.sync.aligned.m16n8k16.row.col.f32.bf16.bf16.f32 "
        "{%0,%1,%2,%3},{%4,%5,%6,%7},{%8,%9},{%0,%1,%2,%3};"
        : "+f"(d0), "+f"(d1), "+f"(d2), "+f"(d3)
        : "r"(a0), "r"(a1), "r"(a2), "r"(a3), "r"(b0), "r"(b1));
}

extern __shared__ char dynsm[];

__global__ __launch_bounds__(NTHREADS, 2)
void session_graph_kernel(const int* __restrict__ inputs,
                          const int* __restrict__ adj,
                          const float* __restrict__ A_attr,
                          const float* __restrict__ emb,
                          const float* __restrict__ attr_emb,
                          const float* __restrict__ a0,
                          const float* __restrict__ a1,
                          const float* __restrict__ a2,
                          const float* __restrict__ a3,
                          float* __restrict__ out)
{
    const int tid  = threadIdx.x;
    const int bb   = blockIdx.x;
    const int warp = tid >> 5;
    const int lane = tid & 31;
    const int gq   = lane >> 2;
    const int tq   = lane & 3;

    if (bb < B_SZ) {
        float* alpha = (float*)(dynsm + OFF_ALPHA);
        unsigned char* adjb = (unsigned char*)(dynsm + OFF_ADJ);
        const u64* hu = (const u64*)(dynsm + OFF_HU);

        // ---------------- staging ----------------------------------------
        // ab2[k][ks][tq] : u64 {lo=bf16x2 scaled a at cols bc+2tq, hi at bc+8+2tq}
        if (tid < 256) {
            int k = tid >> 6, r = tid & 63, ks = r >> 2, q = r & 3;
            const float* a = (k == 0) ? a0 : (k == 1) ? a1 : (k == 2) ? a2 : a3;
            float s = (ks < 8) ? 0.6f : 0.4f;
            int bc = (ks & 7) * 16;
            u32 lo = bpack(s * a[bc + 2 * q],     s * a[bc + 2 * q + 1]);
            u32 hi = bpack(s * a[bc + 8 + 2 * q], s * a[bc + 8 + 2 * q + 1]);
            *(u64*)(dynsm + OFF_AB2 + ((k * 16 + ks) * 4 + q) * 8) = ((u64)hi << 32) | lo;
        }
        {
            const int* ag = adj + bb * NN;
            for (int idx = tid; idx < NN; idx += NTHREADS)
                adjb[idx] = (unsigned char)ag[idx];
        }
        {
            const int* inrow = inputs + bb * N_SZ;
            const u64* embu = (const u64*)emb;
            for (int idx = tid; idx < N_SZ * 64; idx += NTHREADS) {
                int i = idx >> 6, c = idx & 63;          // c: pair of fp32 cols 2c,2c+1
                int node = inrow[i];
                u64 e = embu[(size_t)node * 64 + c];
                *(u64*)(dynsm + OFF_HU + ((size_t)i * HUSTR + c) * 8) = e;
                *(u32*)(dynsm + OFF_HB16 + i * HBSTR + c * 4)       = bcvt(e);
                *(u32*)(dynsm + OFF_HB16 + i * HBSTR + 256 + c * 4) = bcvt(f2_abs(e));
            }
            for (int idx = tid; idx < 6 * 132; idx += NTHREADS) {    // zero rows 50..55
                int i = 50 + idx / 132, c = idx % 132;
                *(u32*)(dynsm + OFF_HB16 + i * HBSTR + c * 4) = 0;
            }
        }
        for (int idx = tid; idx < N_SZ * ASTR; idx += NTHREADS)
            alpha[idx] = NEGV;
        __syncthreads();

        // ---------------- phase 2: MMA with ldmatrix operands --------------
        // M = 4 k-blocks x 64 rows -> 16 k-pure mtiles; N = 7 ntiles (3 pairs + 1 single)
        const u32 hbb = s2u(dynsm + OFF_HB16);
        const int grp = lane >> 3, rsel = lane & 7;
        for (int u = warp; u < 64; u += 16) {
            int mt = u >> 2, np = u & 3;
            int kk = (mt >> 2) + 1;
            int ib = (mt & 3) * 16;
            int arow = ib + rsel + ((grp & 1) << 3);
            if (arow >= N_SZ) arow = 0;                     // outputs discarded
            u32 aaddr  = hbb + arow * HBSTR + ((grp >> 1) << 4);
            int n0 = np * 2;                                 // ntile 0,2,4,6
            u32 baddr0 = hbb + (n0 * 8 + rsel) * HBSTR + ((lane & 8) << 1);
            u32 baddr1 = baddr0 + 8 * HBSTR;
            bool pair = (np < 3);
            const u64* abp = (const u64*)(dynsm + OFF_AB2 + (mt >> 2) * 512) + tq;

            float dA0 = 0.f, dA1 = 0.f, dA2 = 0.f, dA3 = 0.f;
            float dB0 = 0.f, dB1 = 0.f, dB2 = 0.f, dB3 = 0.f;
            #pragma unroll
            for (int ks = 0; ks < 16; ++ks) {
                u64 ab = abp[ks * 4];
                u32 ablo = (u32)ab, abhi = (u32)(ab >> 32);
                u32 h0, h1, h2, h3;
                ldsm4(h0, h1, h2, h3, aaddr + ks * 32);
                u32 fa0 = bmul(h0, ablo), fa1 = bmul(h1, ablo);
                u32 fa2 = bmul(h2, abhi), fa3 = bmul(h3, abhi);
                u32 b0, b1;
                ldsm2(b0, b1, baddr0 + ks * 32);
                mma16816(dA0, dA1, dA2, dA3, fa0, fa1, fa2, fa3, b0, b1);
                if (pair) {
                    u32 c0, c1;
                    ldsm2(c0, c1, baddr1 + ks * 32);
                    mma16816(dB0, dB1, dB2, dB3, fa0, fa1, fa2, fa3, c0, c1);
                }
            }
            // epilogue: masked scatter into alpha
            int i0 = ib + gq, i1 = i0 + 8;
            int j0 = n0 * 8 + 2 * tq;
            float dv[2][4] = {{dA0, dA1, dA2, dA3}, {dB0, dB1, dB2, dB3}};
            int tmax = pair ? 2 : 1;
            #pragma unroll
            for (int t = 0; t < 2; ++t) {
                if (t >= tmax) break;
                int j = j0 + 8 * t;
                if (j < N_SZ) {
                    bool jn = (j + 1 < N_SZ);
                    if (i0 < N_SZ) {
                        if (adjb[i0 * N_SZ + j] == kk)       alpha[i0 * ASTR + j]     = dv[t][0];
                        if (jn && adjb[i0 * N_SZ + j + 1] == kk) alpha[i0 * ASTR + j + 1] = dv[t][1];
                    }
                    if (i1 < N_SZ) {
                        if (adjb[i1 * N_SZ + j] == kk)       alpha[i1 * ASTR + j]     = dv[t][2];
                        if (jn && adjb[i1 * N_SZ + j + 1] == kk) alpha[i1 * ASTR + j + 1] = dv[t][3];
                    }
                }
            }
        }
        __syncthreads();

        // ---------------- phase 3: row softmax -----------------------------
        for (int i = warp; i < N_SZ; i += 16) {
            float v0 = alpha[i * ASTR + lane];
            float v1 = (lane < N_SZ - 32) ? alpha[i * ASTR + 32 + lane] : NEGV;
            float m = fmaxf(v0, v1);
            #pragma unroll
            for (int off = 16; off > 0; off >>= 1)
                m = fmaxf(m, __shfl_xor_sync(0xFFFFFFFFu, m, off));
            float e0 = __expf(v0 - m);
            float e1 = (lane < N_SZ - 32) ? __expf(v1 - m) : 0.f;
            float ss = e0 + e1;
            #pragma unroll
            for (int off = 16; off > 0; off >>= 1)
                ss += __shfl_xor_sync(0xFFFFFFFFu, ss, off);
            float inv = 1.0f / ss;
            alpha[i * ASTR + lane] = e0 * inv;
            if (lane < N_SZ - 32)
                alpha[i * ASTR + 32 + lane] = e1 * inv;
        }
        __syncthreads();

        // ---------------- phase 4: out = alpha @ h (fp32) ------------------
        u64* outu = (u64*)out;
        for (int base = 0; base < N_SZ; base += 32) {
            int r0 = base + 2 * warp;
            int r1 = r0 + 1;
            if (r1 < N_SZ) {
                const float* ar0 = &alpha[r0 * ASTR];
                const float* ar1 = &alpha[r1 * ASTR];
                u64 aL0 = 0, aH0 = 0, aL1 = 0, aH1 = 0;
                #pragma unroll 5
                for (int j = 0; j < N_SZ; ++j) {
                    u64 hlo = hu[j * HUSTR + lane];
                    u64 hhi = hu[j * HUSTR + 32 + lane];
                    u64 c0 = f2_dup(ar0[j]);
                    u64 c1 = f2_dup(ar1[j]);
                    aL0 = f2_fma(c0, hlo, aL0);
                    aH0 = f2_fma(c0, hhi, aH0);
                    aL1 = f2_fma(c1, hlo, aL1);
                    aH1 = f2_fma(c1, hhi, aH1);
                }
                size_t ob = (size_t)bb * (N_SZ * 64);
                outu[ob + r0 * 64 + lane]      = aL0;
                outu[ob + r0 * 64 + 32 + lane] = aH0;
                outu[ob + r1 * 64 + lane]      = aL1;
                outu[ob + r1 * 64 + 32 + lane] = aH1;
            }
        }
    } else {
        // ---------------- attr_sess = A_attr @ attr_emb --------------------
        u64* red = (u64*)dynsm;
        const int ab    = bb - B_SZ;
        const int r0row = ab * 4;
        const int kbase = warp * 125;
        const float4* W4 = ((const float4*)attr_emb);
        const float* Ar0 = A_attr + (size_t)(r0row + 0) * MAX_ATTR + kbase;
        const float* Ar1 = A_attr + (size_t)(r0row + 1) * MAX_ATTR + kbase;
        const float* Ar2 = A_attr + (size_t)(r0row + 2) * MAX_ATTR + kbase;
        const float* Ar3 = A_attr + (size_t)(r0row + 3) * MAX_ATTR + kbase;

        u64 acc[4][2] = {{0,0},{0,0},{0,0},{0,0}};
        #pragma unroll 5
        for (int k = 0; k < 125; ++k) {
            float4 w = W4[(size_t)(kbase + k) * 32 + lane];
            u64 wl = f2_pack(w.x, w.y);
            u64 wh = f2_pack(w.z, w.w);
            u64 c0 = f2_dup(Ar0[k]);
            u64 c1 = f2_dup(Ar1[k]);
            u64 c2 = f2_dup(Ar2[k]);
            u64 c3 = f2_dup(Ar3[k]);
            acc[0][0] = f2_fma(c0, wl, acc[0][0]); acc[0][1] = f2_fma(c0, wh, acc[0][1]);
            acc[1][0] = f2_fma(c1, wl, acc[1][0]); acc[1][1] = f2_fma(c1, wh, acc[1][1]);
            acc[2][0] = f2_fma(c2, wl, acc[2][0]); acc[2][1] = f2_fma(c2, wh, acc[2][1]);
            acc[3][0] = f2_fma(c3, wl, acc[3][0]); acc[3][1] = f2_fma(c3, wh, acc[3][1]);
        }
        #pragma unroll
        for (int r = 0; r < 4; ++r) {
            red[((warp * 4) + r) * 64 + 2 * lane]     = acc[r][0];
            red[((warp * 4) + r) * 64 + 2 * lane + 1] = acc[r][1];
        }
        __syncthreads();
        if (warp < 4) {
            int row = warp;
            u64 s0 = 0, s1 = 0;
            #pragma unroll
            for (int s = 0; s < 16; ++s) {
                s0 = f2_add(s0, red[(s * 4 + row) * 64 + 2 * lane]);
                s1 = f2_add(s1, red[(s * 4 + row) * 64 + 2 * lane + 1]);
            }
            u64* outu = (u64*)out;
            size_t ob = (size_t)B_SZ * (N_SZ * 64) + (size_t)(r0row + row) * 64;
            outu[ob + 2 * lane]     = s0;
            outu[ob + 2 * lane + 1] = s1;
        }
    }
}

extern "C" void kernel_launch(void* const* d_in, const int* in_sizes, int n_in,
                              void* d_out, int out_size)
{
    (void)in_sizes; (void)n_in; (void)out_size;
    const int*   inputs    = (const int*)  d_in[0];
    const int*   adj       = (const int*)  d_in[1];
    // d_in[2] = mask_item (unused by the reference computation)
    const float* A_attr    = (const float*)d_in[3];
    const float* emb       = (const float*)d_in[4];
    const float* attr_emb  = (const float*)d_in[5];
    const float* a0        = (const float*)d_in[6];
    const float* a1        = (const float*)d_in[7];
    const float* a2        = (const float*)d_in[8];
    const float* a3        = (const float*)d_in[9];
    float* out = (float*)d_out;

    cudaFuncSetAttribute(session_graph_kernel,
                         cudaFuncAttributeMaxDynamicSharedMemorySize, SMEM_DYN);
    session_graph_kernel<<<B_SZ + ATTR_BLOCKS, NTHREADS, SMEM_DYN>>>(
        inputs, adj, A_attr, emb, attr_emb, a0, a1, a2, a3, out);
}

// round 7
// speedup vs baseline: 2.4125x; 1.1446x over previous
#include <cuda_runtime.h>

typedef unsigned long long u64;
typedef unsigned int u32;

#define B_SZ 256
#define N_SZ 50
#define NN   (N_SZ * N_SZ)
#define MAX_ATTR 2000
#define NEGV (-9e15f)
#define NTHREADS 512
#define HBSTR 528               // bytes per hb16 row (264 bf16)
#define HUSTR 65                // u64 stride per fp32 h row
#define ASTR  56                // alpha row stride (f32)

// ---- dynamic smem layout ---------------------------------------------------
#define OFF_HB16  0
#define SZ_HB16   (56 * HBSTR)                 // 29568
#define OFF_HU    (OFF_HB16 + SZ_HB16)
#define SZ_HU     (N_SZ * HUSTR * 8)           // 26000
#define OFF_AB2   (OFF_HU + SZ_HU)
#define SZ_AB2    (4 * 16 * 4 * 8)             // 2048
#define OFF_ALPHA (OFF_AB2 + SZ_AB2)
#define SZ_ALPHA  (N_SZ * ASTR * 4)            // 11200
#define OFF_ADJ   (OFF_ALPHA + SZ_ALPHA)
#define SZ_ADJ    2560
#define OFF_RED   (OFF_ADJ + SZ_ADJ)
#define SZ_RED    (16 * 64 * 8)                // 8192
#define SMEM_DYN  (OFF_RED + SZ_RED)           // 79568

// ---- helpers ---------------------------------------------------------------
__device__ __forceinline__ u64 f2_fma(u64 a, u64 b, u64 c) {
    u64 d; asm("fma.rn.f32x2 %0,%1,%2,%3;" : "=l"(d) : "l"(a), "l"(b), "l"(c)); return d;
}
__device__ __forceinline__ u64 f2_add(u64 a, u64 b) {
    u64 d; asm("add.rn.f32x2 %0,%1,%2;" : "=l"(d) : "l"(a), "l"(b)); return d;
}
__device__ __forceinline__ u64 f2_abs(u64 a) { return a & 0x7FFFFFFF7FFFFFFFull; }
__device__ __forceinline__ u64 f2_dup(float a) {
    u64 d; asm("mov.b64 %0,{%1,%1};" : "=l"(d) : "f"(a)); return d;
}
__device__ __forceinline__ u64 f2_pack(float x, float y) {
    u64 d; asm("mov.b64 %0,{%1,%2};" : "=l"(d) : "f"(x), "f"(y)); return d;
}
__device__ __forceinline__ float2 f2_unpack(u64 a) {
    float2 r; asm("mov.b64 {%0,%1},%2;" : "=f"(r.x), "=f"(r.y) : "l"(a)); return r;
}
__device__ __forceinline__ u32 bpack(float lo, float hi) {
    u32 r; asm("cvt.rn.bf16x2.f32 %0,%1,%2;" : "=r"(r) : "f"(hi), "f"(lo)); return r;
}
__device__ __forceinline__ u32 bcvt(u64 v) {
    float2 p = f2_unpack(v); return bpack(p.x, p.y);
}
__device__ __forceinline__ u32 bmul(u32 a, u32 b) {
    u32 d; asm("mul.bf16x2 %0,%1,%2;" : "=r"(d) : "r"(a), "r"(b)); return d;
}
__device__ __forceinline__ u32 s2u(const void* p) {
    u32 a; asm("{.reg .u64 t; cvta.to.shared.u64 t,%1; cvt.u32.u64 %0,t;}" : "=r"(a) : "l"(p));
    return a;
}
__device__ __forceinline__ void ldsm4(u32& r0, u32& r1, u32& r2, u32& r3, u32 addr) {
    asm volatile("ldmatrix.sync.aligned.m8n8.x4.shared.b16 {%0,%1,%2,%3},[%4];"
                 : "=r"(r0), "=r"(r1), "=r"(r2), "=r"(r3) : "r"(addr));
}
__device__ __forceinline__ void ldsm2(u32& r0, u32& r1, u32 addr) {
    asm volatile("ldmatrix.sync.aligned.m8n8.x2.shared.b16 {%0,%1},[%2];"
                 : "=r"(r0), "=r"(r1) : "r"(addr));
}
__device__ __forceinline__ void mma16816(float& d0, float& d1, float& d2, float& d3,
                                         u32 a0, u32 a1, u32 a2, u32 a3, u32 b0, u32 b1) {
    asm("mma.sync.aligned.m16n8k16.row.col.f32.bf16.bf16.f32 "
        "{%0,%1,%2,%3},{%4,%5,%6,%7},{%8,%9},{%0,%1,%2,%3};"
        : "+f"(d0), "+f"(d1), "+f"(d2), "+f"(d3)
        : "r"(a0), "r"(a1), "r"(a2), "r"(a3), "r"(b0), "r"(b1));
}

extern __shared__ char dynsm[];

// phase-4 quad-row worker
template<int NR>
__device__ __forceinline__ void quad_rows(const u64* __restrict__ hu,
                                          const float* __restrict__ alpha,
                                          u64* __restrict__ outu,
                                          int bb, int r0, int lane)
{
    u64 acc[NR][2];
    #pragma unroll
    for (int r = 0; r < NR; ++r) { acc[r][0] = 0; acc[r][1] = 0; }
    #pragma unroll 2
    for (int jb = 0; jb < 12; ++jb) {
        float4 a4[NR];
        #pragma unroll
        for (int r = 0; r < NR; ++r)
            a4[r] = *(const float4*)(alpha + (r0 + r) * ASTR + jb * 4);
        #pragma unroll
        for (int jj = 0; jj < 4; ++jj) {
            int j = jb * 4 + jj;
            u64 hlo = hu[j * HUSTR + lane];
            u64 hhi = hu[j * HUSTR + 32 + lane];
            #pragma unroll
            for (int r = 0; r < NR; ++r) {
                float av = (jj == 0) ? a4[r].x : (jj == 1) ? a4[r].y : (jj == 2) ? a4[r].z : a4[r].w;
                u64 c = f2_dup(av);
                acc[r][0] = f2_fma(c, hlo, acc[r][0]);
                acc[r][1] = f2_fma(c, hhi, acc[r][1]);
            }
        }
    }
    #pragma unroll
    for (int jj = 0; jj < 2; ++jj) {              // tail j = 48, 49
        int j = 48 + jj;
        u64 hlo = hu[j * HUSTR + lane];
        u64 hhi = hu[j * HUSTR + 32 + lane];
        #pragma unroll
        for (int r = 0; r < NR; ++r) {
            u64 c = f2_dup(alpha[(r0 + r) * ASTR + j]);
            acc[r][0] = f2_fma(c, hlo, acc[r][0]);
            acc[r][1] = f2_fma(c, hhi, acc[r][1]);
        }
    }
    size_t ob = (size_t)bb * (N_SZ * 64);
    #pragma unroll
    for (int r = 0; r < NR; ++r) {
        outu[ob + (r0 + r) * 64 + lane]      = acc[r][0];
        outu[ob + (r0 + r) * 64 + 32 + lane] = acc[r][1];
    }
}

__global__ __launch_bounds__(NTHREADS, 2)
void session_graph_kernel(const int* __restrict__ inputs,
                          const int* __restrict__ adj,
                          const float* __restrict__ A_attr,
                          const float* __restrict__ emb,
                          const float* __restrict__ attr_emb,
                          const float* __restrict__ a0,
                          const float* __restrict__ a1,
                          const float* __restrict__ a2,
                          const float* __restrict__ a3,
                          float* __restrict__ out)
{
    const int tid  = threadIdx.x;
    const int bb   = blockIdx.x;
    const int warp = tid >> 5;
    const int lane = tid & 31;
    const int gq   = lane >> 2;
    const int tq   = lane & 3;

    float* alpha = (float*)(dynsm + OFF_ALPHA);
    unsigned char* adjb = (unsigned char*)(dynsm + OFF_ADJ);
    const u64* hu = (const u64*)(dynsm + OFF_HU);
    u64* red = (u64*)(dynsm + OFF_RED);
    u64* outu = (u64*)out;

    // ---------------- staging -----------------------------------------
    if (tid < 256) {
        int k = tid >> 6, r = tid & 63, ks = r >> 2, q = r & 3;
        const float* a = (k == 0) ? a0 : (k == 1) ? a1 : (k == 2) ? a2 : a3;
        float s = (ks < 8) ? 0.6f : 0.4f;
        int bc = (ks & 7) * 16;
        u32 lo = bpack(s * a[bc + 2 * q],     s * a[bc + 2 * q + 1]);
        u32 hi = bpack(s * a[bc + 8 + 2 * q], s * a[bc + 8 + 2 * q + 1]);
        *(u64*)(dynsm + OFF_AB2 + ((k * 16 + ks) * 4 + q) * 8) = ((u64)hi << 32) | lo;
    }
    {
        const int* ag = adj + bb * NN;
        for (int idx = tid; idx < NN; idx += NTHREADS)
            adjb[idx] = (unsigned char)ag[idx];
    }
    {
        const int* inrow = inputs + bb * N_SZ;
        const u64* embu = (const u64*)emb;
        for (int idx = tid; idx < N_SZ * 64; idx += NTHREADS) {
            int i = idx >> 6, c = idx & 63;
            int node = inrow[i];
            u64 e = embu[(size_t)node * 64 + c];
            *(u64*)(dynsm + OFF_HU + ((size_t)i * HUSTR + c) * 8) = e;
            *(u32*)(dynsm + OFF_HB16 + i * HBSTR + c * 4)       = bcvt(e);
            *(u32*)(dynsm + OFF_HB16 + i * HBSTR + 256 + c * 4) = bcvt(f2_abs(e));
        }
        for (int idx = tid; idx < 6 * 132; idx += NTHREADS) {    // zero rows 50..55
            int i = 50 + idx / 132, c = idx % 132;
            *(u32*)(dynsm + OFF_HB16 + i * HBSTR + c * 4) = 0;
        }
    }
    for (int idx = tid; idx < N_SZ * ASTR; idx += NTHREADS)
        alpha[idx] = NEGV;
    __syncthreads();

    // ---------------- phase 2: warp = (i-block, ntile-pair); k resident x2
    {
        const u32 hbb = s2u(dynsm + OFF_HB16);
        const int grp = lane >> 3, rsel = lane & 7;
        const int ib = warp >> 2, np = warp & 3;
        int arow = ib * 16 + rsel + ((grp & 1) << 3);
        if (arow >= N_SZ) arow = 0;                     // discarded rows
        const u32 aaddr = hbb + arow * HBSTR + ((grp >> 1) << 4);
        const int nt0 = np * 2;
        const u32 baddr0 = hbb + (nt0 * 8 + rsel) * HBSTR + ((lane & 8) << 1);
        const u32 baddr1 = baddr0 + 8 * HBSTR;
        const bool pair = (np < 3);
        const int i0 = ib * 16 + gq, i1 = i0 + 8;
        const int j0 = nt0 * 8 + 2 * tq;

        #pragma unroll
        for (int kh = 0; kh < 2; ++kh) {
            const u64* abp = (const u64*)(dynsm + OFF_AB2) + (2 * kh) * 64 + tq;
            float dA[2][4], dB[2][4];
            #pragma unroll
            for (int s = 0; s < 2; ++s)
                #pragma unroll
                for (int x = 0; x < 4; ++x) { dA[s][x] = 0.f; dB[s][x] = 0.f; }

            #pragma unroll 4
            for (int ks = 0; ks < 16; ++ks) {
                u32 h0, h1, h2, h3;
                ldsm4(h0, h1, h2, h3, aaddr + ks * 32);
                u64 ab0 = abp[ks * 4];
                u64 ab1 = abp[ks * 4 + 64];
                u32 lo0 = (u32)ab0, hi0 = (u32)(ab0 >> 32);
                u32 lo1 = (u32)ab1, hi1 = (u32)(ab1 >> 32);
                u32 f00 = bmul(h0, lo0), f01 = bmul(h1, lo0);
                u32 f02 = bmul(h2, hi0), f03 = bmul(h3, hi0);
                u32 f10 = bmul(h0, lo1), f11 = bmul(h1, lo1);
                u32 f12 = bmul(h2, hi1), f13 = bmul(h3, hi1);
                u32 b0, b1;
                ldsm2(b0, b1, baddr0 + ks * 32);
                mma16816(dA[0][0], dA[0][1], dA[0][2], dA[0][3], f00, f01, f02, f03, b0, b1);
                mma16816(dA[1][0], dA[1][1], dA[1][2], dA[1][3], f10, f11, f12, f13, b0, b1);
                if (pair) {
                    u32 c0, c1;
                    ldsm2(c0, c1, baddr1 + ks * 32);
                    mma16816(dB[0][0], dB[0][1], dB[0][2], dB[0][3], f00, f01, f02, f03, c0, c1);
                    mma16816(dB[1][0], dB[1][1], dB[1][2], dB[1][3], f10, f11, f12, f13, c0, c1);
                }
            }
            // epilogue
            #pragma unroll
            for (int s = 0; s < 2; ++s) {
                int kk = 2 * kh + s + 1;
                if (j0 < N_SZ) {
                    bool jn = (j0 + 1 < N_SZ);
                    if (i0 < N_SZ) {
                        if (adjb[i0 * N_SZ + j0] == kk)          alpha[i0 * ASTR + j0]     = dA[s][0];
                        if (jn && adjb[i0 * N_SZ + j0 + 1] == kk) alpha[i0 * ASTR + j0 + 1] = dA[s][1];
                    }
                    if (i1 < N_SZ) {
                        if (adjb[i1 * N_SZ + j0] == kk)          alpha[i1 * ASTR + j0]     = dA[s][2];
                        if (jn && adjb[i1 * N_SZ + j0 + 1] == kk) alpha[i1 * ASTR + j0 + 1] = dA[s][3];
                    }
                }
                if (pair) {
                    int j2 = j0 + 8;
                    if (i0 < N_SZ) {
                        if (adjb[i0 * N_SZ + j2] == kk)      alpha[i0 * ASTR + j2]     = dB[s][0];
                        if (adjb[i0 * N_SZ + j2 + 1] == kk)  alpha[i0 * ASTR + j2 + 1] = dB[s][1];
                    }
                    if (i1 < N_SZ) {
                        if (adjb[i1 * N_SZ + j2] == kk)      alpha[i1 * ASTR + j2]     = dB[s][2];
                        if (adjb[i1 * N_SZ + j2 + 1] == kk)  alpha[i1 * ASTR + j2 + 1] = dB[s][3];
                    }
                }
            }
        }
    }
    __syncthreads();

    // ---------------- phase 3: row softmax ------------------------------
    for (int i = warp; i < N_SZ; i += 16) {
        float v0 = alpha[i * ASTR + lane];
        float v1 = (lane < N_SZ - 32) ? alpha[i * ASTR + 32 + lane] : NEGV;
        float m = fmaxf(v0, v1);
        #pragma unroll
        for (int off = 16; off > 0; off >>= 1)
            m = fmaxf(m, __shfl_xor_sync(0xFFFFFFFFu, m, off));
        float e0 = __expf(v0 - m);
        float e1 = (lane < N_SZ - 32) ? __expf(v1 - m) : 0.f;
        float ss = e0 + e1;
        #pragma unroll
        for (int off = 16; off > 0; off >>= 1)
            ss += __shfl_xor_sync(0xFFFFFFFFu, ss, off);
        float inv = 1.0f / ss;
        alpha[i * ASTR + lane] = e0 * inv;
        if (lane < N_SZ - 32)
            alpha[i * ASTR + 32 + lane] = e1 * inv;
    }
    __syncthreads();

    // ---------------- phase 4: out = alpha @ h (quad rows) --------------
    if (warp < 12)      quad_rows<4>(hu, alpha, outu, bb, warp * 4, lane);
    else if (warp == 12) quad_rows<2>(hu, alpha, outu, bb, 48, lane);

    // ---------------- attr row bb: partial GEMM over K ------------------
    {
        const int kbase = warp * 125;
        const float4* W4 = (const float4*)attr_emb;
        const float* Ar = A_attr + (size_t)bb * MAX_ATTR + kbase;
        u64 acc0 = 0, acc1 = 0;
        #pragma unroll 5
        for (int k = 0; k < 125; ++k) {
            float4 w = W4[(size_t)(kbase + k) * 32 + lane];
            u64 c = f2_dup(Ar[k]);
            acc0 = f2_fma(c, f2_pack(w.x, w.y), acc0);
            acc1 = f2_fma(c, f2_pack(w.z, w.w), acc1);
        }
        red[warp * 64 + 2 * lane]     = acc0;
        red[warp * 64 + 2 * lane + 1] = acc1;
    }
    __syncthreads();
    if (warp == 0) {
        u64 s0 = 0, s1 = 0;
        #pragma unroll
        for (int s = 0; s < 16; ++s) {
            s0 = f2_add(s0, red[s * 64 + 2 * lane]);
            s1 = f2_add(s1, red[s * 64 + 2 * lane + 1]);
        }
        size_t ob = (size_t)B_SZ * (N_SZ * 64) + (size_t)bb * 64;
        outu[ob + 2 * lane]     = s0;
        outu[ob + 2 * lane + 1] = s1;
    }
}

extern "C" void kernel_launch(void* const* d_in, const int* in_sizes, int n_in,
                              void* d_out, int out_size)
{
    (void)in_sizes; (void)n_in; (void)out_size;
    const int*   inputs    = (const int*)  d_in[0];
    const int*   adj       = (const int*)  d_in[1];
    // d_in[2] = mask_item (unused by the reference computation)
    const float* A_attr    = (const float*)d_in[3];
    const float* emb       = (const float*)d_in[4];
    const float* attr_emb  = (const float*)d_in[5];
    const float* a0        = (const float*)d_in[6];
    const float* a1        = (const float*)d_in[7];
    const float* a2        = (const float*)d_in[8];
    const float* a3        = (const float*)d_in[9];
    float* out = (float*)d_out;

    cudaFuncSetAttribute(session_graph_kernel,
                         cudaFuncAttributeMaxDynamicSharedMemorySize, SMEM_DYN);
    session_graph_kernel<<<B_SZ, NTHREADS, SMEM_DYN>>>(
        inputs, adj, A_attr, emb, attr_emb, a0, a1, a2, a3, out);
}

// round 9
// speedup vs baseline: 2.8000x; 1.1606x over previous
#include <cuda_runtime.h>

typedef unsigned long long u64;
typedef unsigned int u32;

#define B_SZ 256
#define N_SZ 50
#define NN   (N_SZ * N_SZ)
#define MAX_ATTR 2000
#define NEGV (-9e15f)
#define NTHREADS 512
#define ATTR_BLOCKS 32
#define ATTR_ROWS 8
#define HBSTR 528               // bytes per hb16 row (264 bf16)
#define HUSTR 65                // u64 stride per fp32 h row
#define ASTR  56                // alpha row stride (f32)

// ---- dynamic smem layout (session) -----------------------------------------
#define OFF_HB16  0
#define SZ_HB16   (56 * HBSTR)                 // 29568
#define OFF_HU    (OFF_HB16 + SZ_HB16)
#define SZ_HU     (N_SZ * HUSTR * 8)           // 26000
#define OFF_AB2   (OFF_HU + SZ_HU)
#define SZ_AB2    (4 * 16 * 4 * 8)             // 2048
#define OFF_ALPHA (OFF_AB2 + SZ_AB2)
#define SZ_ALPHA  (N_SZ * ASTR * 4)            // 11200
#define OFF_ADJ   (OFF_ALPHA + SZ_ALPHA)
#define SZ_ADJ    2560
#define SMEM_DYN  (OFF_ADJ + SZ_ADJ)           // 71376
// attr blocks alias dynsm[0..65536) for A-rows then the reduction buffer.

// ---- helpers ---------------------------------------------------------------
__device__ __forceinline__ u64 f2_fma(u64 a, u64 b, u64 c) {
    u64 d; asm("fma.rn.f32x2 %0,%1,%2,%3;" : "=l"(d) : "l"(a), "l"(b), "l"(c)); return d;
}
__device__ __forceinline__ u64 f2_add(u64 a, u64 b) {
    u64 d; asm("add.rn.f32x2 %0,%1,%2;" : "=l"(d) : "l"(a), "l"(b)); return d;
}
__device__ __forceinline__ u64 f2_abs(u64 a) { return a & 0x7FFFFFFF7FFFFFFFull; }
__device__ __forceinline__ u64 f2_dup(float a) {
    u64 d; asm("mov.b64 %0,{%1,%1};" : "=l"(d) : "f"(a)); return d;
}
__device__ __forceinline__ float2 f2_unpack(u64 a) {
    float2 r; asm("mov.b64 {%0,%1},%2;" : "=f"(r.x), "=f"(r.y) : "l"(a)); return r;
}
__device__ __forceinline__ u32 bpack(float lo, float hi) {
    u32 r; asm("cvt.rn.bf16x2.f32 %0,%1,%2;" : "=r"(r) : "f"(hi), "f"(lo)); return r;
}
__device__ __forceinline__ u32 bcvt(u64 v) {
    float2 p = f2_unpack(v); return bpack(p.x, p.y);
}
__device__ __forceinline__ u32 bmul(u32 a, u32 b) {
    u32 d; asm("mul.bf16x2 %0,%1,%2;" : "=r"(d) : "r"(a), "r"(b)); return d;
}
__device__ __forceinline__ u32 s2u(const void* p) {
    u32 a; asm("{.reg .u64 t; cvta.to.shared.u64 t,%1; cvt.u32.u64 %0,t;}" : "=r"(a) : "l"(p));
    return a;
}
__device__ __forceinline__ void ldsm4(u32& r0, u32& r1, u32& r2, u32& r3, u32 addr) {
    asm volatile("ldmatrix.sync.aligned.m8n8.x4.shared.b16 {%0,%1,%2,%3},[%4];"
                 : "=r"(r0), "=r"(r1), "=r"(r2), "=r"(r3) : "r"(addr));
}
__device__ __forceinline__ void ldsm2(u32& r0, u32& r1, u32 addr) {
    asm volatile("ldmatrix.sync.aligned.m8n8.x2.shared.b16 {%0,%1},[%2];"
                 : "=r"(r0), "=r"(r1) : "r"(addr));
}
__device__ __forceinline__ void mma16816(float& d0, float& d1, float& d2, float& d3,
                                         u32 a0, u32 a1, u32 a2, u32 a3, u32 b0, u32 b1) {
    asm("mma.sync.aligned.m16n8k16.row.col.f32.bf16.bf16.f32 "
        "{%0,%1,%2,%3},{%4,%5,%6,%7},{%8,%9},{%0,%1,%2,%3};"
        : "+f"(d0), "+f"(d1), "+f"(d2), "+f"(d3)
        : "r"(a0), "r"(a1), "r"(a2), "r"(a3), "r"(b0), "r"(b1));
}

extern __shared__ char dynsm[];

// phase-4 multi-row worker
template<int NR>
__device__ __forceinline__ void quad_rows(const u64* __restrict__ hu,
                                          const float* __restrict__ alpha,
                                          u64* __restrict__ outu,
                                          int bb, int r0, int lane)
{
    u64 acc[NR][2];
    #pragma unroll
    for (int r = 0; r < NR; ++r) { acc[r][0] = 0; acc[r][1] = 0; }
    #pragma unroll 2
    for (int jb = 0; jb < 12; ++jb) {
        float4 a4[NR];
        #pragma unroll
        for (int r = 0; r < NR; ++r)
            a4[r] = *(const float4*)(alpha + (r0 + r) * ASTR + jb * 4);
        #pragma unroll
        for (int jj = 0; jj < 4; ++jj) {
            int j = jb * 4 + jj;
            u64 hlo = hu[j * HUSTR + lane];
            u64 hhi = hu[j * HUSTR + 32 + lane];
            #pragma unroll
            for (int r = 0; r < NR; ++r) {
                float av = (jj == 0) ? a4[r].x : (jj == 1) ? a4[r].y : (jj == 2) ? a4[r].z : a4[r].w;
                u64 c = f2_dup(av);
                acc[r][0] = f2_fma(c, hlo, acc[r][0]);
                acc[r][1] = f2_fma(c, hhi, acc[r][1]);
            }
        }
    }
    #pragma unroll
    for (int jj = 0; jj < 2; ++jj) {              // tail j = 48, 49
        int j = 48 + jj;
        u64 hlo = hu[j * HUSTR + lane];
        u64 hhi = hu[j * HUSTR + 32 + lane];
        #pragma unroll
        for (int r = 0; r < NR; ++r) {
            u64 c = f2_dup(alpha[(r0 + r) * ASTR + j]);
            acc[r][0] = f2_fma(c, hlo, acc[r][0]);
            acc[r][1] = f2_fma(c, hhi, acc[r][1]);
        }
    }
    size_t ob = (size_t)bb * (N_SZ * 64);
    #pragma unroll
    for (int r = 0; r < NR; ++r) {
        outu[ob + (r0 + r) * 64 + lane]      = acc[r][0];
        outu[ob + (r0 + r) * 64 + 32 + lane] = acc[r][1];
    }
}

__global__ __launch_bounds__(NTHREADS, 2)
void session_graph_kernel(const int* __restrict__ inputs,
                          const int* __restrict__ adj,
                          const float* __restrict__ A_attr,
                          const float* __restrict__ emb,
                          const float* __restrict__ attr_emb,
                          const float* __restrict__ a0,
                          const float* __restrict__ a1,
                          const float* __restrict__ a2,
                          const float* __restrict__ a3,
                          float* __restrict__ out)
{
    const int tid  = threadIdx.x;
    const int bb   = blockIdx.x;
    const int warp = tid >> 5;
    const int lane = tid & 31;
    const int gq   = lane >> 2;
    const int tq   = lane & 3;
    u64* outu = (u64*)out;

    if (bb < B_SZ) {
        float* alpha = (float*)(dynsm + OFF_ALPHA);
        unsigned char* adjb = (unsigned char*)(dynsm + OFF_ADJ);
        const u64* hu = (const u64*)(dynsm + OFF_HU);

        // ---------------- staging -----------------------------------------
        if (tid < 256) {
            int k = tid >> 6, r = tid & 63, ks = r >> 2, q = r & 3;
            const float* a = (k == 0) ? a0 : (k == 1) ? a1 : (k == 2) ? a2 : a3;
            float s = (ks < 8) ? 0.6f : 0.4f;
            int bc = (ks & 7) * 16;
            u32 lo = bpack(s * a[bc + 2 * q],     s * a[bc + 2 * q + 1]);
            u32 hi = bpack(s * a[bc + 8 + 2 * q], s * a[bc + 8 + 2 * q + 1]);
            *(u64*)(dynsm + OFF_AB2 + ((k * 16 + ks) * 4 + q) * 8) = ((u64)hi << 32) | lo;
        }
        {
            const int* ag = adj + bb * NN;
            for (int idx = tid; idx < NN; idx += NTHREADS)
                adjb[idx] = (unsigned char)ag[idx];
        }
        {
            const int* inrow = inputs + bb * N_SZ;
            const u64* embu = (const u64*)emb;
            for (int idx = tid; idx < N_SZ * 64; idx += NTHREADS) {
                int i = idx >> 6, c = idx & 63;
                int node = inrow[i];
                u64 e = embu[(size_t)node * 64 + c];
                *(u64*)(dynsm + OFF_HU + ((size_t)i * HUSTR + c) * 8) = e;
                *(u32*)(dynsm + OFF_HB16 + i * HBSTR + c * 4)       = bcvt(e);
                *(u32*)(dynsm + OFF_HB16 + i * HBSTR + 256 + c * 4) = bcvt(f2_abs(e));
            }
            for (int idx = tid; idx < 6 * 132; idx += NTHREADS) {    // zero rows 50..55
                int i = 50 + idx / 132, c = idx % 132;
                *(u32*)(dynsm + OFF_HB16 + i * HBSTR + c * 4) = 0;
            }
        }
        for (int idx = tid; idx < N_SZ * ASTR; idx += NTHREADS)
            alpha[idx] = NEGV;
        __syncthreads();

        // ---------------- phase 2: warp = (i-block, ntile-pair); k resident x2
        {
            const u32 hbb = s2u(dynsm + OFF_HB16);
            const int grp = lane >> 3, rsel = lane & 7;
            const int ib = warp >> 2, np = warp & 3;
            int arow = ib * 16 + rsel + ((grp & 1) << 3);
            if (arow >= N_SZ) arow = 0;                     // discarded rows
            const u32 aaddr = hbb + arow * HBSTR + ((grp >> 1) << 4);
            const int nt0 = np * 2;
            const u32 baddr0 = hbb + (nt0 * 8 + rsel) * HBSTR + ((lane & 8) << 1);
            const u32 baddr1 = baddr0 + 8 * HBSTR;
            const bool pair = (np < 3);
            const int i0 = ib * 16 + gq, i1 = i0 + 8;
            const int j0 = nt0 * 8 + 2 * tq;

            #pragma unroll
            for (int kh = 0; kh < 2; ++kh) {
                const u64* abp = (const u64*)(dynsm + OFF_AB2) + (2 * kh) * 64 + tq;
                float dA[2][4], dB[2][4];
                #pragma unroll
                for (int s = 0; s < 2; ++s)
                    #pragma unroll
                    for (int x = 0; x < 4; ++x) { dA[s][x] = 0.f; dB[s][x] = 0.f; }

                #pragma unroll 4
                for (int ks = 0; ks < 16; ++ks) {
                    u32 h0, h1, h2, h3;
                    ldsm4(h0, h1, h2, h3, aaddr + ks * 32);
                    u64 ab0 = abp[ks * 4];
                    u64 ab1 = abp[ks * 4 + 64];
                    u32 lo0 = (u32)ab0, hi0 = (u32)(ab0 >> 32);
                    u32 lo1 = (u32)ab1, hi1 = (u32)(ab1 >> 32);
                    u32 f00 = bmul(h0, lo0), f01 = bmul(h1, lo0);
                    u32 f02 = bmul(h2, hi0), f03 = bmul(h3, hi0);
                    u32 f10 = bmul(h0, lo1), f11 = bmul(h1, lo1);
                    u32 f12 = bmul(h2, hi1), f13 = bmul(h3, hi1);
                    u32 b0, b1;
                    ldsm2(b0, b1, baddr0 + ks * 32);
                    mma16816(dA[0][0], dA[0][1], dA[0][2], dA[0][3], f00, f01, f02, f03, b0, b1);
                    mma16816(dA[1][0], dA[1][1], dA[1][2], dA[1][3], f10, f11, f12, f13, b0, b1);
                    if (pair) {
                        u32 c0, c1;
                        ldsm2(c0, c1, baddr1 + ks * 32);
                        mma16816(dB[0][0], dB[0][1], dB[0][2], dB[0][3], f00, f01, f02, f03, c0, c1);
                        mma16816(dB[1][0], dB[1][1], dB[1][2], dB[1][3], f10, f11, f12, f13, c0, c1);
                    }
                }
                // epilogue
                #pragma unroll
                for (int s = 0; s < 2; ++s) {
                    int kk = 2 * kh + s + 1;
                    if (j0 < N_SZ) {
                        bool jn = (j0 + 1 < N_SZ);
                        if (i0 < N_SZ) {
                            if (adjb[i0 * N_SZ + j0] == kk)          alpha[i0 * ASTR + j0]     = dA[s][0];
                            if (jn && adjb[i0 * N_SZ + j0 + 1] == kk) alpha[i0 * ASTR + j0 + 1] = dA[s][1];
                        }
                        if (i1 < N_SZ) {
                            if (adjb[i1 * N_SZ + j0] == kk)          alpha[i1 * ASTR + j0]     = dA[s][2];
                            if (jn && adjb[i1 * N_SZ + j0 + 1] == kk) alpha[i1 * ASTR + j0 + 1] = dA[s][3];
                        }
                    }
                    if (pair) {
                        int j2 = j0 + 8;
                        if (i0 < N_SZ) {
                            if (adjb[i0 * N_SZ + j2] == kk)      alpha[i0 * ASTR + j2]     = dB[s][0];
                            if (adjb[i0 * N_SZ + j2 + 1] == kk)  alpha[i0 * ASTR + j2 + 1] = dB[s][1];
                        }
                        if (i1 < N_SZ) {
                            if (adjb[i1 * N_SZ + j2] == kk)      alpha[i1 * ASTR + j2]     = dB[s][2];
                            if (adjb[i1 * N_SZ + j2 + 1] == kk)  alpha[i1 * ASTR + j2 + 1] = dB[s][3];
                        }
                    }
                }
            }
        }
        __syncthreads();

        // ---------------- phase 3: row softmax ------------------------------
        for (int i = warp; i < N_SZ; i += 16) {
            float v0 = alpha[i * ASTR + lane];
            float v1 = (lane < N_SZ - 32) ? alpha[i * ASTR + 32 + lane] : NEGV;
            float m = fmaxf(v0, v1);
            #pragma unroll
            for (int off = 16; off > 0; off >>= 1)
                m = fmaxf(m, __shfl_xor_sync(0xFFFFFFFFu, m, off));
            float e0 = __expf(v0 - m);
            float e1 = (lane < N_SZ - 32) ? __expf(v1 - m) : 0.f;
            float ss = e0 + e1;
            #pragma unroll
            for (int off = 16; off > 0; off >>= 1)
                ss += __shfl_xor_sync(0xFFFFFFFFu, ss, off);
            float inv = 1.0f / ss;
            alpha[i * ASTR + lane] = e0 * inv;
            if (lane < N_SZ - 32)
                alpha[i * ASTR + 32 + lane] = e1 * inv;
        }
        __syncthreads();

        // ---------------- phase 4: out = alpha @ h (5 rows x 10 warps) -----
        if (warp < 10) quad_rows<5>(hu, alpha, outu, bb, warp * 5, lane);
    } else {
        // ---------------- attr GEMM: 8 rows per block ----------------------
        const int ab    = bb - B_SZ;
        const int r0row = ab * ATTR_ROWS;
        float* As = (float*)dynsm;                  // 8 x 2000 f32 = 64000 B
        u64*   red = (u64*)dynsm;                   // aliases As after sync

        // stage 8 contiguous A rows
        {
            const float4* Ag = (const float4*)(A_attr + (size_t)r0row * MAX_ATTR);
            float4* As4 = (float4*)As;
            for (int idx = tid; idx < ATTR_ROWS * MAX_ATTR / 4; idx += NTHREADS)
                As4[idx] = Ag[idx];
        }
        __syncthreads();

        // partial GEMM: 4-k chunks interleaved across warps
        u64 acc[ATTR_ROWS][2];
        #pragma unroll
        for (int r = 0; r < ATTR_ROWS; ++r) { acc[r][0] = 0; acc[r][1] = 0; }
        {
            const uint4* Wg = (const uint4*)attr_emb;
            for (int c = warp; c < MAX_ATTR / 4; c += 16) {
                int k = c * 4;
                uint4 w0 = Wg[(size_t)(k + 0) * 32 + lane];
                uint4 w1 = Wg[(size_t)(k + 1) * 32 + lane];
                uint4 w2 = Wg[(size_t)(k + 2) * 32 + lane];
                uint4 w3 = Wg[(size_t)(k + 3) * 32 + lane];
                u64 w0l = ((u64)w0.y << 32) | w0.x, w0h = ((u64)w0.w << 32) | w0.z;
                u64 w1l = ((u64)w1.y << 32) | w1.x, w1h = ((u64)w1.w << 32) | w1.z;
                u64 w2l = ((u64)w2.y << 32) | w2.x, w2h = ((u64)w2.w << 32) | w2.z;
                u64 w3l = ((u64)w3.y << 32) | w3.x, w3h = ((u64)w3.w << 32) | w3.z;
                #pragma unroll
                for (int r = 0; r < ATTR_ROWS; ++r) {
                    float4 av = *(const float4*)(As + r * MAX_ATTR + k);
                    u64 cx = f2_dup(av.x), cy = f2_dup(av.y);
                    u64 cz = f2_dup(av.z), cw = f2_dup(av.w);
                    acc[r][0] = f2_fma(cx, w0l, acc[r][0]); acc[r][1] = f2_fma(cx, w0h, acc[r][1]);
                    acc[r][0] = f2_fma(cy, w1l, acc[r][0]); acc[r][1] = f2_fma(cy, w1h, acc[r][1]);
                    acc[r][0] = f2_fma(cz, w2l, acc[r][0]); acc[r][1] = f2_fma(cz, w2h, acc[r][1]);
                    acc[r][0] = f2_fma(cw, w3l, acc[r][0]); acc[r][1] = f2_fma(cw, w3h, acc[r][1]);
                }
            }
        }
        __syncthreads();                            // all reads of As done

        // write partials: red[warp][row][2*lane .. +1]
        #pragma unroll
        for (int r = 0; r < ATTR_ROWS; ++r) {
            u64* myred = red + ((size_t)(warp * ATTR_ROWS + r)) * 64;
            myred[2 * lane]     = acc[r][0];
            myred[2 * lane + 1] = acc[r][1];
        }
        __syncthreads();

        // reduce 16 partials: thread -> (row, u64 col)
        {
            int row = tid >> 6, col = tid & 63;
            u64 s = 0;
            #pragma unroll
            for (int w = 0; w < 16; ++w)
                s = f2_add(s, red[((size_t)(w * ATTR_ROWS + row)) * 64 + col]);
            size_t ob = (size_t)B_SZ * (N_SZ * 64) + (size_t)(r0row + row) * 64;
            outu[ob + col] = s;
        }
    }
}

extern "C" void kernel_launch(void* const* d_in, const int* in_sizes, int n_in,
                              void* d_out, int out_size)
{
    (void)in_sizes; (void)n_in; (void)out_size;
    const int*   inputs    = (const int*)  d_in[0];
    const int*   adj       = (const int*)  d_in[1];
    // d_in[2] = mask_item (unused by the reference computation)
    const float* A_attr    = (const float*)d_in[3];
    const float* emb       = (const float*)d_in[4];
    const float* attr_emb  = (const float*)d_in[5];
    const float* a0        = (const float*)d_in[6];
    const float* a1        = (const float*)d_in[7];
    const float* a2        = (const float*)d_in[8];
    const float* a3        = (const float*)d_in[9];
    float* out = (float*)d_out;

    cudaFuncSetAttribute(session_graph_kernel,
                         cudaFuncAttributeMaxDynamicSharedMemorySize, SMEM_DYN);
    session_graph_kernel<<<B_SZ + ATTR_BLOCKS, NTHREADS, SMEM_DYN>>>(
        inputs, adj, A_attr, emb, attr_emb, a0, a1, a2, a3, out);
}